// round 1
// baseline (speedup 1.0000x reference)
#include <cuda_runtime.h>
#include <cuda_bf16.h>
#include <cstdint>

// Embedding lookup: out[row, :] = weight[ids[row], :]
//   ids:    [8192] int32   (4 x 2048)
//   weight: [32000, 768] float32
//   out:    [8192, 768] float32
//
// 768 floats = 192 float4 per row. One CTA per row, 192 threads,
// each thread moves one float4. Fully coalesced 16B accesses.

static constexpr int DIM      = 768;
static constexpr int VEC_DIM  = DIM / 4;   // 192 float4 per row

__global__ __launch_bounds__(VEC_DIM) void embedding_gather_kernel(
    const int* __restrict__ ids,
    const float4* __restrict__ weight,
    float4* __restrict__ out)
{
    const int row = blockIdx.x;
    const int id  = ids[row];                      // broadcast load (all threads same addr)
    const float4* __restrict__ src = weight + (size_t)id * VEC_DIM;
    float4* __restrict__ dst       = out    + (size_t)row * VEC_DIM;
    dst[threadIdx.x] = __ldg(&src[threadIdx.x]);
}

extern "C" void kernel_launch(void* const* d_in, const int* in_sizes, int n_in,
                              void* d_out, int out_size)
{
    const int*    ids    = (const int*)d_in[0];       // [4*2048] int32
    const float4* weight = (const float4*)d_in[1];    // [32000, 768] f32 as float4
    float4*       out    = (float4*)d_out;            // [8192, 768] f32 as float4

    const int n_rows = in_sizes[0];                   // 8192
    embedding_gather_kernel<<<n_rows, VEC_DIM>>>(ids, weight, out);
}

// round 2
// speedup vs baseline: 1.1347x; 1.1347x over previous
#include <cuda_runtime.h>
#include <cuda_bf16.h>
#include <cstdint>

// Embedding lookup: out[row, :] = weight[ids[row], :]
//   ids:    [8192] int32, weight: [32000, 768] f32, out: [8192, 768] f32
//
// Latency-fix vs R1: one CTA handles 16 rows. ids for all 16 rows loaded
// once into shared, then each of 192 threads issues 16 INDEPENDENT
// LDG.128s (MLP=16) buffered in registers, then 16 coalesced STG.128s.

static constexpr int DIM     = 768;
static constexpr int VEC     = DIM / 4;   // 192 float4 per row
static constexpr int ROWS    = 16;        // rows per CTA

__global__ __launch_bounds__(VEC, 2) void embedding_gather_kernel(
    const int* __restrict__ ids,
    const float4* __restrict__ weight,
    float4* __restrict__ out)
{
    __shared__ int sid[ROWS];

    const int base = blockIdx.x * ROWS;
    if (threadIdx.x < ROWS)
        sid[threadIdx.x] = ids[base + threadIdx.x];
    __syncthreads();

    const int c = threadIdx.x;   // column (float4 index) this thread owns

    // Batch all 16 independent row loads first (MLP=16 per thread).
    float4 buf[ROWS];
#pragma unroll
    for (int r = 0; r < ROWS; r++) {
        const float4* __restrict__ src = weight + (size_t)sid[r] * VEC;
        buf[r] = __ldg(&src[c]);
    }

    // Then 16 coalesced stores.
#pragma unroll
    for (int r = 0; r < ROWS; r++) {
        out[(size_t)(base + r) * VEC + c] = buf[r];
    }
}

extern "C" void kernel_launch(void* const* d_in, const int* in_sizes, int n_in,
                              void* d_out, int out_size)
{
    const int*    ids    = (const int*)d_in[0];     // [8192] int32
    const float4* weight = (const float4*)d_in[1];  // [32000,768] f32 as float4
    float4*       out    = (float4*)d_out;          // [8192,768] f32 as float4

    const int n_rows = in_sizes[0];                 // 8192
    const int n_ctas = n_rows / ROWS;               // 512
    embedding_gather_kernel<<<n_ctas, VEC>>>(ids, weight, out);
}

// round 3
// speedup vs baseline: 1.3985x; 1.2325x over previous
#include <cuda_runtime.h>
#include <cuda_bf16.h>
#include <cstdint>

// Embedding gather via TMA bulk copies:
//   out[row, :] = weight[ids[row], :],  row-size 3072 B.
// One single-warp CTA per 8 rows. Each row: cp.async.bulk G->S (mbarrier
// complete_tx), then cp.async.bulk S->G (bulk_group). No register staging,
// no LDG/STG data path.

static constexpr int DIM          = 768;
static constexpr int ROW_BYTES    = DIM * 4;              // 3072
static constexpr int ROWS_PER_CTA = 8;
static constexpr int BUF_BYTES    = ROWS_PER_CTA * ROW_BYTES;  // 24576

__global__ __launch_bounds__(32) void emb_tma_kernel(
    const int* __restrict__ ids,
    const float* __restrict__ weight,
    float* __restrict__ out,
    int n_rows)
{
    __shared__ __align__(128) unsigned char buf[BUF_BYTES];
    __shared__ __align__(8)  unsigned long long mbar[ROWS_PER_CTA];

    const int base = blockIdx.x * ROWS_PER_CTA;
    if (threadIdx.x != 0) return;   // single-thread CTA logic (bulk ops are per-thread)

    uint32_t smem_buf  = (uint32_t)__cvta_generic_to_shared(buf);
    uint32_t smem_mbar = (uint32_t)__cvta_generic_to_shared(mbar);

    // Init one mbarrier per row (arrive count 1).
#pragma unroll
    for (int s = 0; s < ROWS_PER_CTA; s++) {
        asm volatile("mbarrier.init.shared.b64 [%0], 1;"
                     :: "r"(smem_mbar + s * 8) : "memory");
    }
    // Make mbarrier init visible to the async (TMA) proxy.
    asm volatile("fence.proxy.async.shared::cta;" ::: "memory");

    // Preload ids (independent loads; ids array is L2-hot).
    int id[ROWS_PER_CTA];
#pragma unroll
    for (int s = 0; s < ROWS_PER_CTA; s++)
        id[s] = __ldg(&ids[base + s]);

    // Issue all G->S bulk copies (deep MLP: 8 x 3KB in flight per CTA).
#pragma unroll
    for (int s = 0; s < ROWS_PER_CTA; s++) {
        uint32_t mb  = smem_mbar + s * 8;
        uint32_t dst = smem_buf + s * ROW_BYTES;
        const void* src = (const char*)weight + (size_t)id[s] * ROW_BYTES;
        asm volatile("mbarrier.arrive.expect_tx.shared.b64 _, [%0], %1;"
                     :: "r"(mb), "r"(ROW_BYTES) : "memory");
        asm volatile(
            "cp.async.bulk.shared::cta.global.mbarrier::complete_tx::bytes "
            "[%0], [%1], %2, [%3];"
            :: "r"(dst), "l"(src), "r"(ROW_BYTES), "r"(mb) : "memory");
    }

    // Drain: as each row lands, stream it back out with a bulk S->G copy.
#pragma unroll
    for (int s = 0; s < ROWS_PER_CTA; s++) {
        uint32_t mb = smem_mbar + s * 8;
        // Wait phase-parity 0 on this row's mbarrier.
        uint32_t done = 0;
        while (!done) {
            asm volatile(
                "{\n\t"
                ".reg .pred p;\n\t"
                "mbarrier.try_wait.parity.acquire.cta.shared::cta.b64 p, [%1], 0, 0x989680;\n\t"
                "selp.b32 %0, 1, 0, p;\n\t"
                "}"
                : "=r"(done) : "r"(mb) : "memory");
        }
        void* dstg = (char*)out + (size_t)(base + s) * ROW_BYTES;
        uint32_t srcs = smem_buf + s * ROW_BYTES;
        asm volatile(
            "cp.async.bulk.global.shared::cta.bulk_group [%0], [%1], %2;"
            :: "l"(dstg), "r"(srcs), "r"(ROW_BYTES) : "memory");
    }
    asm volatile("cp.async.bulk.commit_group;" ::: "memory");
    // SMEM must outlive the S->G reads: drain before CTA exit.
    asm volatile("cp.async.bulk.wait_group 0;" ::: "memory");
}

extern "C" void kernel_launch(void* const* d_in, const int* in_sizes, int n_in,
                              void* d_out, int out_size)
{
    const int*   ids    = (const int*)d_in[0];     // [8192] int32
    const float* weight = (const float*)d_in[1];   // [32000, 768] f32
    float*       out    = (float*)d_out;           // [8192, 768] f32

    const int n_rows = in_sizes[0];                // 8192
    const int n_ctas = n_rows / ROWS_PER_CTA;      // 1024
    emb_tma_kernel<<<n_ctas, 32>>>(ids, weight, out, n_rows);
}